// round 1
// baseline (speedup 1.0000x reference)
#include <cuda_runtime.h>
#include <cuda_bf16.h>
#include <cstdint>

// Problem constants (fixed shapes from reference)
#define SQ   8192          // total sequence
#define DMODEL 1152
#define NH   16
#define DH   72
#define QKV3 3456          // 3*DMODEL
#define LCHUNK 1024
#define NCHUNK 8

// Scratch (device globals; no cudaMalloc allowed)
__device__ float g_qkv[(size_t)SQ * QKV3];       // [S, 3, H, DH]
__device__ float g_attn[(size_t)SQ * DMODEL];    // [S, H*DH]

// ---------------------------------------------------------------------------
// SGEMM: C[M,N] = A[M,K] @ W[N,K]^T + bias[N]
// Both A and W are K-major (row-major with K contiguous).
// 128x128 block tile, BK=8, 256 threads, 8x8 per-thread microtile.
// ---------------------------------------------------------------------------
#define GBM 128
#define GBN 128
#define GBK 8

__global__ __launch_bounds__(256) void sgemm_bias_kernel(
    const float* __restrict__ A, const float* __restrict__ W,
    const float* __restrict__ bias, float* __restrict__ C,
    int M, int N, int K)
{
    __shared__ float As[GBK][GBM];
    __shared__ float Bs[GBK][GBN];

    const int tid = threadIdx.x;
    const int bm = blockIdx.y * GBM;
    const int bn = blockIdx.x * GBN;

    // global->smem loader mapping: 256 threads, one float4 each per matrix
    const int lr = tid >> 1;            // 0..127 (tile row)
    const int lc = (tid & 1) * 4;       // 0 or 4 (k offset)
    const float* Aptr = A + (size_t)(bm + lr) * K + lc;
    const float* Wptr = W + (size_t)(bn + lr) * K + lc;

    const int ty = tid >> 4, tx = tid & 15;
    const int rm = ty * 8, rn = tx * 8;

    float acc[8][8];
#pragma unroll
    for (int i = 0; i < 8; i++)
#pragma unroll
        for (int j = 0; j < 8; j++) acc[i][j] = 0.f;

    // prefetch first slab
    float4 av = *(const float4*)(Aptr);
    float4 wv = *(const float4*)(Wptr);

    for (int k0 = 0; k0 < K; k0 += GBK) {
        As[lc + 0][lr] = av.x; As[lc + 1][lr] = av.y;
        As[lc + 2][lr] = av.z; As[lc + 3][lr] = av.w;
        Bs[lc + 0][lr] = wv.x; Bs[lc + 1][lr] = wv.y;
        Bs[lc + 2][lr] = wv.z; Bs[lc + 3][lr] = wv.w;
        __syncthreads();

        if (k0 + GBK < K) {                // prefetch next slab (overlap with FMAs)
            av = *(const float4*)(Aptr + k0 + GBK);
            wv = *(const float4*)(Wptr + k0 + GBK);
        }

        float ra[8], rb[8];
#pragma unroll
        for (int kk = 0; kk < GBK; kk++) {
            *(float4*)&ra[0] = *(const float4*)&As[kk][rm];
            *(float4*)&ra[4] = *(const float4*)&As[kk][rm + 4];
            *(float4*)&rb[0] = *(const float4*)&Bs[kk][rn];
            *(float4*)&rb[4] = *(const float4*)&Bs[kk][rn + 4];
#pragma unroll
            for (int i = 0; i < 8; i++)
#pragma unroll
                for (int j = 0; j < 8; j++)
                    acc[i][j] += ra[i] * rb[j];
        }
        __syncthreads();
    }

    // epilogue with bias, float4 stores
#pragma unroll
    for (int i = 0; i < 8; i++) {
        const size_t row = (size_t)(bm + rm + i);
        float* cptr = C + row * N + bn + rn;
        const float* bptr = bias + bn + rn;
#pragma unroll
        for (int j4 = 0; j4 < 2; j4++) {
            float4 o;
            o.x = acc[i][j4 * 4 + 0] + bptr[j4 * 4 + 0];
            o.y = acc[i][j4 * 4 + 1] + bptr[j4 * 4 + 1];
            o.z = acc[i][j4 * 4 + 2] + bptr[j4 * 4 + 2];
            o.w = acc[i][j4 * 4 + 3] + bptr[j4 * 4 + 3];
            *(float4*)(cptr + j4 * 4) = o;
        }
    }
}

// ---------------------------------------------------------------------------
// RoPE on q and k in-place inside g_qkv. Layout [S, 3, H, DH].
// out[d]    = x[d]*cos[d]    - x[d+36]*sin[d]      (d < 36)
// out[d+36] = x[d+36]*cos[d+36] + x[d]*sin[d+36]
// ---------------------------------------------------------------------------
__global__ __launch_bounds__(256) void rope_kernel(
    float* __restrict__ qkv, const float* __restrict__ cosp,
    const float* __restrict__ sinp)
{
    const int idx = blockIdx.x * blockDim.x + threadIdx.x;
    const int total = SQ * NH * (DH / 2);
    if (idx >= total) return;
    const int d = idx % (DH / 2);
    const int t = idx / (DH / 2);
    const int h = t % NH;
    const int s = t / NH;

    const float c1 = cosp[s * DH + d];
    const float s1 = sinp[s * DH + d];
    const float c2 = cosp[s * DH + d + 36];
    const float s2 = sinp[s * DH + d + 36];

    size_t base = (size_t)s * QKV3 + h * DH;   // q
#pragma unroll
    for (int w = 0; w < 2; w++) {
        float x1 = qkv[base + d];
        float x2 = qkv[base + d + 36];
        qkv[base + d]      = x1 * c1 - x2 * s1;
        qkv[base + d + 36] = x2 * c2 + x1 * s2;
        base += DMODEL;                         // k
    }
}

// ---------------------------------------------------------------------------
// Flash-style attention. One block per (q-tile of 64, chunk*head).
// BQ=64 query rows, BK=32 key tile, online softmax, O in registers.
// ---------------------------------------------------------------------------
#define BQ  64
#define BKT 32
#define DHP 80   // padded head dim for V / O columns (16 threads x 5)

__global__ __launch_bounds__(256) void attn_kernel(
    const float* __restrict__ qkv, float* __restrict__ out)
{
    __shared__ float sQ[DH][BQ];        // transposed [d][m]
    __shared__ float sK[DH][BKT];       // transposed [d][n]
    __shared__ float sV[BKT][DHP];      // [k][d], zero padded d>=72
    __shared__ float sS[BQ][34];        // probs (cols 0..31 used, stride 34)
    __shared__ float sM[BQ], sL[BQ], sScale[BQ];

    const int tid = threadIdx.x;
    const int qt = blockIdx.x;          // 0..15
    const int chh = blockIdx.y;         // 0..127
    const int chunk = chh >> 4, h = chh & 15;
    const size_t rowbase = (size_t)chunk * LCHUNK;
    const float* Qb = qkv + rowbase * QKV3 + h * DH;
    const float* Kb = Qb + DMODEL;
    const float* Vb = Qb + 2 * DMODEL;
    const int q0 = qt * BQ;

    for (int idx = tid; idx < BQ * DH; idx += 256) {
        const int m = idx / DH, d = idx - m * DH;
        sQ[d][m] = Qb[(size_t)(q0 + m) * QKV3 + d];
    }
    if (tid < BQ) { sM[tid] = -1e30f; sL[tid] = 0.f; }

    const int ty = tid >> 4, tx = tid & 15;
    const int m0 = ty * 4;              // 4 q rows
    const int n0 = tx * 2;              // 2 score cols
    const int c0 = tx * 5;              // 5 output cols (padded)

    float acc[4][5];
#pragma unroll
    for (int i = 0; i < 4; i++)
#pragma unroll
        for (int j = 0; j < 5; j++) acc[i][j] = 0.f;

    const float scl = rsqrtf((float)DH);
    __syncthreads();

    for (int kt = 0; kt < LCHUNK / BKT; kt++) {
        const int k0 = kt * BKT;
        // load K (transposed) and V (padded) tiles
        for (int idx = tid; idx < BKT * DH; idx += 256) {
            const int n = idx / DH, d = idx - n * DH;
            sK[d][n] = Kb[(size_t)(k0 + n) * QKV3 + d];
        }
        for (int idx = tid; idx < BKT * DHP; idx += 256) {
            const int n = idx / DHP, d = idx - n * DHP;
            sV[n][d] = (d < DH) ? Vb[(size_t)(k0 + n) * QKV3 + d] : 0.f;
        }
        __syncthreads();

        // GEMM1: S = Q @ K^T  (4x2 per thread)
        float sa00 = 0.f, sa01 = 0.f, sa10 = 0.f, sa11 = 0.f;
        float sa20 = 0.f, sa21 = 0.f, sa30 = 0.f, sa31 = 0.f;
#pragma unroll
        for (int d = 0; d < DH; d++) {
            const float4 a = *(const float4*)&sQ[d][m0];
            const float2 b = *(const float2*)&sK[d][n0];
            sa00 += a.x * b.x; sa01 += a.x * b.y;
            sa10 += a.y * b.x; sa11 += a.y * b.y;
            sa20 += a.z * b.x; sa21 += a.z * b.y;
            sa30 += a.w * b.x; sa31 += a.w * b.y;
        }
        sS[m0 + 0][n0] = sa00 * scl; sS[m0 + 0][n0 + 1] = sa01 * scl;
        sS[m0 + 1][n0] = sa10 * scl; sS[m0 + 1][n0 + 1] = sa11 * scl;
        sS[m0 + 2][n0] = sa20 * scl; sS[m0 + 2][n0 + 1] = sa21 * scl;
        sS[m0 + 3][n0] = sa30 * scl; sS[m0 + 3][n0 + 1] = sa31 * scl;
        __syncthreads();

        // online softmax: 4 threads per row, 8 elements each
        {
            const int r = tid >> 2, part = tid & 3;
            float vals[8];
            float mloc = -1e30f;
#pragma unroll
            for (int u = 0; u < 8; u++) {
                vals[u] = sS[r][part * 8 + u];
                mloc = fmaxf(mloc, vals[u]);
            }
            mloc = fmaxf(mloc, __shfl_xor_sync(0xffffffffu, mloc, 1));
            mloc = fmaxf(mloc, __shfl_xor_sync(0xffffffffu, mloc, 2));
            const float mold = sM[r];
            const float mnew = fmaxf(mold, mloc);
            float lsum = 0.f;
#pragma unroll
            for (int u = 0; u < 8; u++) {
                const float p = __expf(vals[u] - mnew);
                sS[r][part * 8 + u] = p;
                lsum += p;
            }
            lsum += __shfl_xor_sync(0xffffffffu, lsum, 1);
            lsum += __shfl_xor_sync(0xffffffffu, lsum, 2);
            if (part == 0) {
                const float sc = __expf(mold - mnew);
                sScale[r] = sc;
                sM[r] = mnew;
                sL[r] = sL[r] * sc + lsum;
            }
        }
        __syncthreads();

        // rescale O, then GEMM2: O += P @ V
#pragma unroll
        for (int i = 0; i < 4; i++) {
            const float sc = sScale[m0 + i];
#pragma unroll
            for (int j = 0; j < 5; j++) acc[i][j] *= sc;
        }
#pragma unroll
        for (int kk = 0; kk < BKT; kk++) {
            const float p0 = sS[m0 + 0][kk];
            const float p1 = sS[m0 + 1][kk];
            const float p2 = sS[m0 + 2][kk];
            const float p3 = sS[m0 + 3][kk];
#pragma unroll
            for (int j = 0; j < 5; j++) {
                const float v = sV[kk][c0 + j];
                acc[0][j] += p0 * v;
                acc[1][j] += p1 * v;
                acc[2][j] += p2 * v;
                acc[3][j] += p3 * v;
            }
        }
        __syncthreads();
    }

    // epilogue: normalize and store [S, H*DH]
#pragma unroll
    for (int i = 0; i < 4; i++) {
        const float inv = 1.f / sL[m0 + i];
        const size_t row = rowbase + q0 + m0 + i;
#pragma unroll
        for (int j = 0; j < 5; j++) {
            const int d = c0 + j;
            if (d < DH)
                out[row * DMODEL + h * DH + d] = acc[i][j] * inv;
        }
    }
}

// ---------------------------------------------------------------------------
// kernel_launch
// inputs: hidden_states[S,D], cos[S,72], sin[S,72], qkv_w[3456,1152],
//         qkv_b[3456], proj_w[1152,1152], proj_b[1152], cu_seqlens[9]
// ---------------------------------------------------------------------------
extern "C" void kernel_launch(void* const* d_in, const int* in_sizes, int n_in,
                              void* d_out, int out_size)
{
    const float* hidden = (const float*)d_in[0];
    const float* cosp   = (const float*)d_in[1];
    const float* sinp   = (const float*)d_in[2];
    const float* qkv_w  = (const float*)d_in[3];
    const float* qkv_b  = (const float*)d_in[4];
    const float* proj_w = (const float*)d_in[5];
    const float* proj_b = (const float*)d_in[6];
    (void)in_sizes; (void)n_in;

    float* qkv = nullptr;
    float* attn = nullptr;
    cudaGetSymbolAddress((void**)&qkv, g_qkv);
    cudaGetSymbolAddress((void**)&attn, g_attn);

    // 1) QKV GEMM + bias: [8192,3456]
    sgemm_bias_kernel<<<dim3(QKV3 / GBN, SQ / GBM), 256>>>(
        hidden, qkv_w, qkv_b, qkv, SQ, QKV3, DMODEL);

    // 2) RoPE on q,k
    {
        const int total = SQ * NH * (DH / 2);
        rope_kernel<<<(total + 255) / 256, 256>>>(qkv, cosp, sinp);
    }

    // 3) attention -> [8192, 1152]
    attn_kernel<<<dim3(LCHUNK / BQ, NCHUNK * NH), 256>>>(qkv, attn);

    // 4) output projection + bias -> d_out
    sgemm_bias_kernel<<<dim3(DMODEL / GBN, SQ / GBM), 256>>>(
        attn, proj_w, proj_b, (float*)d_out, SQ, DMODEL, DMODEL);
}